// round 10
// baseline (speedup 1.0000x reference)
#include <cuda_runtime.h>
#include <cuda_bf16.h>
#include <cstdint>
#include <cstddef>

// ---------------------------------------------------------------------------
// SimpleAttention B=4, N=4096, D=192 — mma.sync bf16, 3-MMA split precision.
// Attention CTA = 64 q-rows; warps split into two independent pipelines
// (even/odd k-tiles) with private staging + named barriers so the tensor pipe
// is never idled by a CTA-wide phase lock. Weight normalization fused as the
// CTA tail (overlaps across the 1.7-wave grid).
// d_out layout: [out (B*N*192) | weights (B*N*N)]
// Softmax without max-subtraction is exact-safe (|logit| <~ 33).
// ---------------------------------------------------------------------------

#define BATCH 4
#define NSEQ  4096
#define DDIM  192
#define NEGV  (-1e9f)
#define BND   (BATCH * NSEQ * DDIM)
#define WSZ   (DDIM * DDIM)

__device__ __align__(256) __nv_bfloat16 g_Ih[3 * BND];
__device__ __align__(256) __nv_bfloat16 g_Il[3 * BND];
__device__ __align__(256) __nv_bfloat16 g_Wh[3 * WSZ];
__device__ __align__(256) __nv_bfloat16 g_Wl[3 * WSZ];
__device__ __align__(256) __nv_bfloat16 g_Qh[BND];
__device__ __align__(256) __nv_bfloat16 g_Ql[BND];
__device__ __align__(256) __nv_bfloat16 g_Kh[BND];
__device__ __align__(256) __nv_bfloat16 g_Kl[BND];
__device__ __align__(256) __nv_bfloat16 g_Vh[BND];
__device__ __align__(256) __nv_bfloat16 g_Vl[BND];

__device__ __forceinline__ void ld4(float* d, const float* s) {
    float4 t = *reinterpret_cast<const float4*>(s);
    d[0]=t.x; d[1]=t.y; d[2]=t.z; d[3]=t.w;
}
__device__ __forceinline__ void st4(float* d, const float* s) {
    float4 t; t.x=s[0]; t.y=s[1]; t.z=s[2]; t.w=s[3];
    *reinterpret_cast<float4*>(d) = t;
}
__device__ __forceinline__ void hl_split(float x, uint16_t& h, uint16_t& l) {
    __nv_bfloat16 hh = __float2bfloat16_rn(x);
    __nv_bfloat16 ll = __float2bfloat16_rn(x - __bfloat162float(hh));
    h = __bfloat16_as_ushort(hh); l = __bfloat16_as_ushort(ll);
}

#define CP_ASYNC16(dst, src) \
    asm volatile("cp.async.cg.shared.global [%0], [%1], 16;" :: "r"(dst), "l"(src) : "memory")
#define CP_COMMIT() asm volatile("cp.async.commit_group;" ::: "memory")
#define CP_WAIT0()  asm volatile("cp.async.wait_group 0;" ::: "memory")

__device__ __forceinline__ void ldsm4(uint32_t f[4], uint32_t addr) {
    asm volatile("ldmatrix.sync.aligned.m8n8.x4.shared.b16 {%0,%1,%2,%3}, [%4];\n"
        : "=r"(f[0]), "=r"(f[1]), "=r"(f[2]), "=r"(f[3]) : "r"(addr));
}
__device__ __forceinline__ void ldsm4t(uint32_t f[4], uint32_t addr) {
    asm volatile("ldmatrix.sync.aligned.m8n8.x4.trans.shared.b16 {%0,%1,%2,%3}, [%4];\n"
        : "=r"(f[0]), "=r"(f[1]), "=r"(f[2]), "=r"(f[3]) : "r"(addr));
}
__device__ __forceinline__ void mma_bf16(float c[4], const uint32_t a[4],
                                         uint32_t b0, uint32_t b1) {
    asm volatile(
        "mma.sync.aligned.m16n8k16.row.col.f32.bf16.bf16.f32 "
        "{%0,%1,%2,%3}, {%4,%5,%6,%7}, {%8,%9}, {%0,%1,%2,%3};\n"
        : "+f"(c[0]), "+f"(c[1]), "+f"(c[2]), "+f"(c[3])
        : "r"(a[0]), "r"(a[1]), "r"(a[2]), "r"(a[3]), "r"(b0), "r"(b1));
}

__device__ __forceinline__ uint32_t sw24(int r, int c) {
    return (uint32_t)(r * 384 + ((((c) & 24) | (((c) ^ (r)) & 7)) << 4));
}

// ---------------------------------------------------------------------------
// Kernel 0: convert inputs + weights to bf16 hi/lo planes.
// ---------------------------------------------------------------------------
__global__ void convert_kernel(const float* __restrict__ q,
                               const float* __restrict__ k,
                               const float* __restrict__ v,
                               const float* __restrict__ qw,
                               const float* __restrict__ kw,
                               const float* __restrict__ vw) {
    const int TOT4 = (3 * BND + 3 * WSZ) / 4;
    int i4 = blockIdx.x * blockDim.x + threadIdx.x;
    if (i4 >= TOT4) return;
    int idx = i4 * 4;
    const float* src; __nv_bfloat16* dh; __nv_bfloat16* dl;
    if (idx < 3 * BND) {
        int r = idx / BND, o = idx - r * BND;
        src = (r == 0 ? q : (r == 1 ? k : v)) + o;
        dh = g_Ih + r * BND + o; dl = g_Il + r * BND + o;
    } else {
        int wi = idx - 3 * BND;
        int r = wi / WSZ, o = wi - r * WSZ;
        src = (r == 0 ? qw : (r == 1 ? kw : vw)) + o;
        dh = g_Wh + r * WSZ + o; dl = g_Wl + r * WSZ + o;
    }
    float4 x = *reinterpret_cast<const float4*>(src);
    uint16_t h[4], l[4];
    hl_split(x.x, h[0], l[0]); hl_split(x.y, h[1], l[1]);
    hl_split(x.z, h[2], l[2]); hl_split(x.w, h[3], l[3]);
    *reinterpret_cast<uint2*>(dh) =
        make_uint2((uint32_t)h[0] | ((uint32_t)h[1] << 16),
                   (uint32_t)h[2] | ((uint32_t)h[3] << 16));
    *reinterpret_cast<uint2*>(dl) =
        make_uint2((uint32_t)l[0] | ((uint32_t)l[1] << 16),
                   (uint32_t)l[2] | ((uint32_t)l[3] << 16));
}

// ---------------------------------------------------------------------------
// Kernel 1: projections via HMMA (unchanged from R9).
// ---------------------------------------------------------------------------
#define PXH 0u
#define PXL 49152u
#define PWH 98304u
#define PWL 135168u
#define PSMEM 172032

__global__ void __launch_bounds__(256, 1)
proj_kernel() {
    extern __shared__ char smem[];
    const uint32_t SB = (uint32_t)__cvta_generic_to_shared(smem);
    const int mat  = blockIdx.z;
    const int row0 = blockIdx.x * 128;
    const int tid  = threadIdx.x;
    const int wid  = tid >> 5, lane = tid & 31;
    const int g = lane >> 2, t = lane & 3;
    const int q2 = lane >> 3, rI = lane & 7;
    const int rb = wid * 16;

    const __nv_bfloat16* Xh = g_Ih + (size_t)mat * BND + (size_t)row0 * DDIM;
    const __nv_bfloat16* Xl = g_Il + (size_t)mat * BND + (size_t)row0 * DDIM;
    const __nv_bfloat16* Wh = g_Wh + mat * WSZ;
    const __nv_bfloat16* Wl = g_Wl + mat * WSZ;
    __nv_bfloat16* Yh = (mat == 0 ? g_Qh : (mat == 1 ? g_Kh : g_Vh));
    __nv_bfloat16* Yl = (mat == 0 ? g_Ql : (mat == 1 ? g_Kl : g_Vl));

    for (int i = tid; i < 6144; i += 256) {
        int plane = i >= 3072;
        int ii = plane ? i - 3072 : i;
        int r = ii / 24, c = ii % 24;
        const __nv_bfloat16* src = (plane ? Xl : Xh) + (size_t)r * DDIM + c * 8;
        CP_ASYNC16(SB + (plane ? PXL : PXH) + sw24(r, c), src);
    }
    for (int i = tid; i < 4608; i += 256) {
        int plane = i >= 2304;
        int ii = plane ? i - 2304 : i;
        int r = ii / 24, c = ii % 24;
        const __nv_bfloat16* src = (plane ? Wl : Wh) + (size_t)r * DDIM + c * 8;
        CP_ASYNC16(SB + (plane ? PWL : PWH) + sw24(r, c), src);
    }
    CP_COMMIT(); CP_WAIT0(); __syncthreads();

    const int rowA = rb + (lane & 15);
    const int cAadd = lane >> 4;
    const int rowW = ((q2 >> 1) << 3) + rI;
    const int cWadd = q2 & 1;

    for (int cc = 0; cc < 2; cc++) {
        float c[12][4];
        #pragma unroll
        for (int ni = 0; ni < 12; ni++)
            #pragma unroll
            for (int j = 0; j < 4; j++) c[ni][j] = 0.f;

        #pragma unroll
        for (int d0 = 0; d0 < 192; d0 += 16) {
            const int ca = (d0 >> 3) + cAadd;
            const int cw = (d0 >> 3) + cWadd;
            uint32_t ah[4], al[4], wh[6][4], wl[6][4];
            ldsm4(ah, SB + PXH + sw24(rowA, ca));
            ldsm4(al, SB + PXL + sw24(rowA, ca));
            #pragma unroll
            for (int nb = 0; nb < 6; nb++) {
                ldsm4(wh[nb], SB + PWH + sw24(nb * 16 + rowW, cw));
                ldsm4(wl[nb], SB + PWL + sw24(nb * 16 + rowW, cw));
            }
            #pragma unroll
            for (int ni = 0; ni < 12; ni++) {
                uint32_t b0h = wh[ni >> 1][(ni & 1) * 2], b1h = wh[ni >> 1][(ni & 1) * 2 + 1];
                uint32_t b0l = wl[ni >> 1][(ni & 1) * 2], b1l = wl[ni >> 1][(ni & 1) * 2 + 1];
                mma_bf16(c[ni], ah, b0h, b1h);
                mma_bf16(c[ni], ah, b0l, b1l);
                mma_bf16(c[ni], al, b0h, b1h);
            }
        }
        __syncthreads();
        if (cc == 0) {
            for (int i = tid; i < 4608; i += 256) {
                int plane = i >= 2304;
                int ii = plane ? i - 2304 : i;
                int r = ii / 24, ch = ii % 24;
                const __nv_bfloat16* src = (plane ? Wl : Wh) + (size_t)(96 + r) * DDIM + ch * 8;
                CP_ASYNC16(SB + (plane ? PWL : PWH) + sw24(r, ch), src);
            }
            CP_COMMIT();
        }
        #pragma unroll
        for (int ni = 0; ni < 12; ni++) {
            #pragma unroll
            for (int hf = 0; hf < 2; hf++) {
                int row = row0 + rb + g + hf * 8;
                int col = cc * 96 + ni * 8 + 2 * t;
                uint16_t h0, l0, h1, l1;
                hl_split(c[ni][hf * 2 + 0], h0, l0);
                hl_split(c[ni][hf * 2 + 1], h1, l1);
                size_t idx = (size_t)row * DDIM + col;
                *reinterpret_cast<uint32_t*>(&Yh[idx]) = (uint32_t)h0 | ((uint32_t)h1 << 16);
                *reinterpret_cast<uint32_t*>(&Yl[idx]) = (uint32_t)l0 | ((uint32_t)l1 << 16);
            }
        }
        if (cc == 0) { CP_WAIT0(); __syncthreads(); }
    }
}

// ---------------------------------------------------------------------------
// Kernel 2: HMMA flash attention, dual independent pipelines + fused norm.
// grid (64, 4), 256 threads. CTA = 64 q-rows. Group gp = wid>>2 handles
// k-tiles with (tile & 1) == gp (32-col tiles, 64 each). Private K/V stages
// and named barriers per group. O/Z merged in smem at the end.
// ---------------------------------------------------------------------------
#define QHOF 0u
#define QLOF 24576u
#define GST  49152u           // group stage base; each group: 49152 bytes
#define KHO  0u               // + gp*49152
#define KLO  12288u
#define VHO  24576u
#define VLO  36864u
#define ZOFS 147456u
#define ASMEM 148480

__global__ void __launch_bounds__(256, 1)
attn_kernel(const float* __restrict__ attn_mask,
            const float* __restrict__ bias,
            const float* __restrict__ o_w,
            float* __restrict__ out,
            float* __restrict__ wout) {
    extern __shared__ char smem[];
    const uint32_t SB = (uint32_t)__cvta_generic_to_shared(smem);
    float* zs = reinterpret_cast<float*>(smem + ZOFS);   // [2][64] partial Z

    const int b    = blockIdx.y;
    const int q0   = blockIdx.x * 64;
    const int tid  = threadIdx.x;
    const int wid  = tid >> 5, lane = tid & 31;
    const int g = lane >> 2, t = lane & 3;
    const int q2 = lane >> 3, rI = lane & 7;
    const int gp = wid >> 2;          // pipeline group
    const int rb = (wid & 3) * 16;    // warp's rows within 64
    const int gtid = tid & 127;

    const size_t bN = (size_t)b * NSEQ;
    const uint32_t KHB = SB + GST + (uint32_t)gp * 49152u + KHO;
    const uint32_t KLB = SB + GST + (uint32_t)gp * 49152u + KLO;
    const uint32_t VHB = SB + GST + (uint32_t)gp * 49152u + VHO;
    const uint32_t VLB = SB + GST + (uint32_t)gp * 49152u + VLO;

    // ---- prologue: stage Q (all threads) + first K tile (per group) ----
    for (int i = tid; i < 3072; i += 256) {
        int plane = i >= 1536;
        int ii = plane ? i - 1536 : i;
        int r = ii / 24, c = ii % 24;
        const __nv_bfloat16* src = (plane ? g_Ql : g_Qh) + (bN + q0 + r) * DDIM + c * 8;
        CP_ASYNC16(SB + (plane ? QLOF : QHOF) + sw24(r, c), src);
    }
    for (int i = gtid; i < 1536; i += 128) {
        int plane = i >= 768;
        int ii = plane ? i - 768 : i;
        int r = ii / 24, c = ii % 24;
        const __nv_bfloat16* src = (plane ? g_Kl : g_Kh) + (bN + gp * 32 + r) * DDIM + c * 8;
        CP_ASYNC16((plane ? KLB : KHB) + sw24(r, c), src);
    }
    CP_COMMIT();
    CP_WAIT0();
    __syncthreads();   // Q + both first-K tiles visible CTA-wide

    const int rowA  = rb + (lane & 15);
    const int cAadd = lane >> 4;
    const int rowK  = ((q2 >> 1) << 3) + rI;
    const int cKadd = q2 & 1;
    const int rVadd = ((q2 & 1) << 3) + rI;
    const int cVadd = q2 >> 1;

    float o[24][4];
    #pragma unroll
    for (int ni = 0; ni < 24; ni++)
        #pragma unroll
        for (int j = 0; j < 4; j++) o[ni][j] = 0.f;
    float zacc[2] = {0.f, 0.f};

    #define BARG() asm volatile("bar.sync %0, %1;" :: "r"(gp + 1), "r"(128u) : "memory")

    for (int kt = 0; kt < 64; kt++) {
        const int k0 = kt * 64 + gp * 32;
        CP_WAIT0();   // K(kt) landed
        BARG();       // group's warps past PV(kt-1): V stage free

        // stage V(kt)
        for (int i = gtid; i < 1536; i += 128) {
            int plane = i >= 768;
            int ii = plane ? i - 768 : i;
            int r = ii / 24, c = ii % 24;
            const __nv_bfloat16* src = (plane ? g_Vl : g_Vh) + (bN + k0 + r) * DDIM + c * 8;
            CP_ASYNC16((plane ? VLB : VHB) + sw24(r, c), src);
        }
        CP_COMMIT();

        // ---- S = Q @ K^T : 16 rows x 32 cols ----
        float s[4][4];
        #pragma unroll
        for (int ni = 0; ni < 4; ni++)
            #pragma unroll
            for (int j = 0; j < 4; j++) s[ni][j] = 0.f;

        #pragma unroll
        for (int d0 = 0; d0 < 192; d0 += 16) {
            const int ca = (d0 >> 3) + cAadd;
            const int ck = (d0 >> 3) + cKadd;
            uint32_t ah[4], al[4], kh[2][4], kl[2][4];
            ldsm4(ah, SB + QHOF + sw24(rowA, ca));
            ldsm4(al, SB + QLOF + sw24(rowA, ca));
            #pragma unroll
            for (int nb = 0; nb < 2; nb++) {
                ldsm4(kh[nb], KHB + sw24(nb * 16 + rowK, ck));
                ldsm4(kl[nb], KLB + sw24(nb * 16 + rowK, ck));
            }
            #pragma unroll
            for (int ni = 0; ni < 4; ni++) {
                uint32_t b0h = kh[ni >> 1][(ni & 1) * 2], b1h = kh[ni >> 1][(ni & 1) * 2 + 1];
                uint32_t b0l = kl[ni >> 1][(ni & 1) * 2], b1l = kl[ni >> 1][(ni & 1) * 2 + 1];
                mma_bf16(s[ni], ah, b0h, b1h);
                mma_bf16(s[ni], ah, b0l, b1l);
                mma_bf16(s[ni], al, b0h, b1h);
            }
        }

        // ---- epilogue: exp -> wout + P fragments in registers ----
        uint32_t ph[2][4], pl[2][4];
        #pragma unroll
        for (int ni = 0; ni < 4; ni++) {
            const int kk = ni >> 1, sub = ni & 1;
            #pragma unroll
            for (int hf = 0; hf < 2; hf++) {
                const int rr = rb + g + hf * 8;
                const size_t off = (bN + q0 + rr) * (size_t)NSEQ + k0 + ni * 8 + 2 * t;
                float2 bb = *reinterpret_cast<const float2*>(&bias[off]);
                float2 mm = *reinterpret_cast<const float2*>(&attn_mask[off]);
                float p0 = __expf(s[ni][hf * 2 + 0] + bb.x + mm.x * NEGV);
                float p1 = __expf(s[ni][hf * 2 + 1] + bb.y + mm.y * NEGV);
                zacc[hf] += p0 + p1;
                *reinterpret_cast<float2*>(&wout[off]) = make_float2(p0, p1);
                uint16_t h0, l0, h1, l1;
                hl_split(p0, h0, l0); hl_split(p1, h1, l1);
                ph[kk][hf + sub * 2] = (uint32_t)h0 | ((uint32_t)h1 << 16);
                pl[kk][hf + sub * 2] = (uint32_t)l0 | ((uint32_t)l1 << 16);
            }
        }

        CP_WAIT0();   // V(kt) landed
        BARG();       // group's warps done with K stage reads

        // stage K(kt+1) for this group (tile k0 + 64)
        if (kt < 63) {
            for (int i = gtid; i < 1536; i += 128) {
                int plane = i >= 768;
                int ii = plane ? i - 768 : i;
                int r = ii / 24, c = ii % 24;
                const __nv_bfloat16* src = (plane ? g_Kl : g_Kh) + (bN + k0 + 64 + r) * DDIM + c * 8;
                CP_ASYNC16((plane ? KLB : KHB) + sw24(r, c), src);
            }
            CP_COMMIT();
        }

        // ---- O += P @ V ----
        #pragma unroll
        for (int nb = 0; nb < 12; nb++) {
            const int cV = cVadd + 2 * nb;
            #pragma unroll
            for (int kk = 0; kk < 2; kk++) {
                const int rV = kk * 16 + rVadd;
                uint32_t vh[4], vl[4];
                ldsm4t(vh, VHB + sw24(rV, cV));
                ldsm4t(vl, VLB + sw24(rV, cV));
                #pragma unroll
                for (int sub = 0; sub < 2; sub++) {
                    const int ni = 2 * nb + sub;
                    uint32_t b0h = vh[sub * 2], b1h = vh[sub * 2 + 1];
                    uint32_t b0l = vl[sub * 2], b1l = vl[sub * 2 + 1];
                    mma_bf16(o[ni], ph[kk], b0h, b1h);
                    mma_bf16(o[ni], ph[kk], b0l, b1l);
                    mma_bf16(o[ni], pl[kk], b0h, b1h);
                }
            }
        }
    }
    #undef BARG

    // ---- partial Z -> smem ----
    {
        float v0 = zacc[0], v1 = zacc[1];
        v0 += __shfl_xor_sync(0xffffffffu, v0, 1);
        v0 += __shfl_xor_sync(0xffffffffu, v0, 2);
        v1 += __shfl_xor_sync(0xffffffffu, v1, 1);
        v1 += __shfl_xor_sync(0xffffffffu, v1, 2);
        if (t == 0) { zs[gp * 64 + rb + g] = v0; zs[gp * 64 + rb + g + 8] = v1; }
    }
    __syncthreads();

    // ---- merge O across groups (group0 raw, then group1 adds + normalizes) ----
    float* OF = reinterpret_cast<float*>(smem);   // 64 x 196 fp32
    if (gp == 0) {
        #pragma unroll
        for (int hf = 0; hf < 2; hf++) {
            const int rr = rb + g + hf * 8;
            #pragma unroll
            for (int ni = 0; ni < 24; ni++) {
                const int col = ni * 8 + 2 * t;
                OF[rr * 196 + col]     = o[ni][hf * 2 + 0];
                OF[rr * 196 + col + 1] = o[ni][hf * 2 + 1];
            }
        }
    }
    __syncthreads();
    if (gp == 1) {
        #pragma unroll
        for (int hf = 0; hf < 2; hf++) {
            const int rr = rb + g + hf * 8;
            const float iz = 1.0f / (zs[rr] + zs[64 + rr]);
            #pragma unroll
            for (int ni = 0; ni < 24; ni++) {
                const int col = ni * 8 + 2 * t;
                OF[rr * 196 + col]     = (OF[rr * 196 + col]     + o[ni][hf * 2 + 0]) * iz;
                OF[rr * 196 + col + 1] = (OF[rr * 196 + col + 1] + o[ni][hf * 2 + 1]) * iz;
            }
        }
    }
    __syncthreads();

    // ---- output projection (SIMT): 64 rows ----
    {
        const int ty = tid >> 4, tx = tid & 15;
        float op[4][12];
        #pragma unroll
        for (int rr = 0; rr < 4; rr++)
            #pragma unroll
            for (int c = 0; c < 12; c++) op[rr][c] = 0.f;

        #pragma unroll 2
        for (int e4 = 0; e4 < 48; e4++) {
            float oa[4][4];
            #pragma unroll
            for (int rr = 0; rr < 4; rr++) ld4(oa[rr], &OF[(ty * 4 + rr) * 196 + e4 * 4]);
            float wv[12][4];
            #pragma unroll
            for (int c = 0; c < 12; c++) ld4(wv[c], &o_w[(size_t)(tx * 12 + c) * DDIM + e4 * 4]);
            #pragma unroll
            for (int dd = 0; dd < 4; dd++)
                #pragma unroll
                for (int rr = 0; rr < 4; rr++)
                    #pragma unroll
                    for (int c = 0; c < 12; c++)
                        op[rr][c] += oa[rr][dd] * wv[c][dd];
        }

        #pragma unroll
        for (int rr = 0; rr < 4; rr++) {
            size_t off = (bN + q0 + ty * 4 + rr) * (size_t)DDIM + tx * 12;
            st4(&out[off],     &op[rr][0]);
            st4(&out[off + 4], &op[rr][4]);
            st4(&out[off + 8], &op[rr][8]);
        }
    }

    // ---- fused weight normalization: rescale this CTA's 64 rows ----
    {
        const int rl = tid >> 2, tc = tid & 3;
        const float izr = 1.0f / (zs[rl] + zs[64 + rl]);
        float4* p = reinterpret_cast<float4*>(wout + (bN + q0 + rl) * (size_t)NSEQ);
        #pragma unroll 4
        for (int j = 0; j < 256; j++) {
            float4 v = p[tc + j * 4];
            v.x *= izr; v.y *= izr; v.z *= izr; v.w *= izr;
            p[tc + j * 4] = v;
        }
    }
}

// ---------------------------------------------------------------------------
extern "C" void kernel_launch(void* const* d_in, const int* in_sizes, int n_in,
                              void* d_out, int out_size) {
    const float* query = (const float*)d_in[0];
    const float* key_t = (const float*)d_in[1];
    const float* value = (const float*)d_in[2];
    const float* mask  = (const float*)d_in[3];
    const float* bias  = (const float*)d_in[4];
    const float* q_w   = (const float*)d_in[5];
    const float* k_w   = (const float*)d_in[6];
    const float* v_w   = (const float*)d_in[7];
    const float* o_w   = (const float*)d_in[8];

    float* out  = (float*)d_out;
    float* wout = (float*)d_out + (size_t)BATCH * NSEQ * DDIM;

    cudaFuncSetAttribute(proj_kernel, cudaFuncAttributeMaxDynamicSharedMemorySize, PSMEM);
    cudaFuncSetAttribute(attn_kernel, cudaFuncAttributeMaxDynamicSharedMemorySize, ASMEM);

    const int TOT4 = (3 * BND + 3 * WSZ) / 4;
    convert_kernel<<<(TOT4 + 255) / 256, 256>>>(query, key_t, value, q_w, k_w, v_w);

    dim3 pgrid((BATCH * NSEQ) / 128, 1, 3);
    proj_kernel<<<pgrid, 256, PSMEM>>>();

    dim3 agrid(NSEQ / 64, BATCH);
    attn_kernel<<<agrid, 256, ASMEM>>>(mask, bias, o_w, out, wout);
}

// round 11
// speedup vs baseline: 1.5651x; 1.5651x over previous
#include <cuda_runtime.h>
#include <cuda_bf16.h>
#include <cstdint>
#include <cstddef>

// ---------------------------------------------------------------------------
// SimpleAttention B=4, N=4096, D=192 — all GEMMs on mma.sync bf16 with 3-MMA
// split precision. Projections: convert->HMMA. Attention: warp-owns-16-rows
// layout, P in registers; weight normalization fused into the CTA tail.
// d_out layout: [out (B*N*192) | weights (B*N*N)]
// Softmax without max-subtraction is exact-safe (|logit| <~ 33).
// ---------------------------------------------------------------------------

#define BATCH 4
#define NSEQ  4096
#define DDIM  192
#define NEGV  (-1e9f)
#define BND   (BATCH * NSEQ * DDIM)
#define WSZ   (DDIM * DDIM)

__device__ __align__(256) __nv_bfloat16 g_Ih[3 * BND];
__device__ __align__(256) __nv_bfloat16 g_Il[3 * BND];
__device__ __align__(256) __nv_bfloat16 g_Wh[3 * WSZ];
__device__ __align__(256) __nv_bfloat16 g_Wl[3 * WSZ];
__device__ __align__(256) __nv_bfloat16 g_Qh[BND];
__device__ __align__(256) __nv_bfloat16 g_Ql[BND];
__device__ __align__(256) __nv_bfloat16 g_Kh[BND];
__device__ __align__(256) __nv_bfloat16 g_Kl[BND];
__device__ __align__(256) __nv_bfloat16 g_Vh[BND];
__device__ __align__(256) __nv_bfloat16 g_Vl[BND];

__device__ __forceinline__ void ld4(float* d, const float* s) {
    float4 t = *reinterpret_cast<const float4*>(s);
    d[0]=t.x; d[1]=t.y; d[2]=t.z; d[3]=t.w;
}
__device__ __forceinline__ void st4(float* d, const float* s) {
    float4 t; t.x=s[0]; t.y=s[1]; t.z=s[2]; t.w=s[3];
    *reinterpret_cast<float4*>(d) = t;
}
__device__ __forceinline__ void hl_split(float x, uint16_t& h, uint16_t& l) {
    __nv_bfloat16 hh = __float2bfloat16_rn(x);
    __nv_bfloat16 ll = __float2bfloat16_rn(x - __bfloat162float(hh));
    h = __bfloat16_as_ushort(hh); l = __bfloat16_as_ushort(ll);
}

#define CP_ASYNC16(dst, src) \
    asm volatile("cp.async.cg.shared.global [%0], [%1], 16;" :: "r"(dst), "l"(src) : "memory")
#define CP_COMMIT() asm volatile("cp.async.commit_group;" ::: "memory")
#define CP_WAIT0()  asm volatile("cp.async.wait_group 0;" ::: "memory")

__device__ __forceinline__ void ldsm4(uint32_t f[4], uint32_t addr) {
    asm volatile("ldmatrix.sync.aligned.m8n8.x4.shared.b16 {%0,%1,%2,%3}, [%4];\n"
        : "=r"(f[0]), "=r"(f[1]), "=r"(f[2]), "=r"(f[3]) : "r"(addr));
}
__device__ __forceinline__ void ldsm4t(uint32_t f[4], uint32_t addr) {
    asm volatile("ldmatrix.sync.aligned.m8n8.x4.trans.shared.b16 {%0,%1,%2,%3}, [%4];\n"
        : "=r"(f[0]), "=r"(f[1]), "=r"(f[2]), "=r"(f[3]) : "r"(addr));
}
__device__ __forceinline__ void mma_bf16(float c[4], const uint32_t a[4],
                                         uint32_t b0, uint32_t b1) {
    asm volatile(
        "mma.sync.aligned.m16n8k16.row.col.f32.bf16.bf16.f32 "
        "{%0,%1,%2,%3}, {%4,%5,%6,%7}, {%8,%9}, {%0,%1,%2,%3};\n"
        : "+f"(c[0]), "+f"(c[1]), "+f"(c[2]), "+f"(c[3])
        : "r"(a[0]), "r"(a[1]), "r"(a[2]), "r"(a[3]), "r"(b0), "r"(b1));
}

__device__ __forceinline__ uint32_t sw24(int r, int c) {
    return (uint32_t)(r * 384 + ((((c) & 24) | (((c) ^ (r)) & 7)) << 4));
}

// ---------------------------------------------------------------------------
// Kernel 0: convert inputs + weights to bf16 hi/lo planes.
// ---------------------------------------------------------------------------
__global__ void convert_kernel(const float* __restrict__ q,
                               const float* __restrict__ k,
                               const float* __restrict__ v,
                               const float* __restrict__ qw,
                               const float* __restrict__ kw,
                               const float* __restrict__ vw) {
    const int TOT4 = (3 * BND + 3 * WSZ) / 4;
    int i4 = blockIdx.x * blockDim.x + threadIdx.x;
    if (i4 >= TOT4) return;
    int idx = i4 * 4;
    const float* src; __nv_bfloat16* dh; __nv_bfloat16* dl;
    if (idx < 3 * BND) {
        int r = idx / BND, o = idx - r * BND;
        src = (r == 0 ? q : (r == 1 ? k : v)) + o;
        dh = g_Ih + r * BND + o; dl = g_Il + r * BND + o;
    } else {
        int wi = idx - 3 * BND;
        int r = wi / WSZ, o = wi - r * WSZ;
        src = (r == 0 ? qw : (r == 1 ? kw : vw)) + o;
        dh = g_Wh + r * WSZ + o; dl = g_Wl + r * WSZ + o;
    }
    float4 x = *reinterpret_cast<const float4*>(src);
    uint16_t h[4], l[4];
    hl_split(x.x, h[0], l[0]); hl_split(x.y, h[1], l[1]);
    hl_split(x.z, h[2], l[2]); hl_split(x.w, h[3], l[3]);
    *reinterpret_cast<uint2*>(dh) =
        make_uint2((uint32_t)h[0] | ((uint32_t)h[1] << 16),
                   (uint32_t)h[2] | ((uint32_t)h[3] << 16));
    *reinterpret_cast<uint2*>(dl) =
        make_uint2((uint32_t)l[0] | ((uint32_t)l[1] << 16),
                   (uint32_t)l[2] | ((uint32_t)l[3] << 16));
}

// ---------------------------------------------------------------------------
// Kernel 1: projections via HMMA.
// ---------------------------------------------------------------------------
#define PXH 0u
#define PXL 49152u
#define PWH 98304u
#define PWL 135168u
#define PSMEM 172032

__global__ void __launch_bounds__(256, 1)
proj_kernel() {
    extern __shared__ char smem[];
    const uint32_t SB = (uint32_t)__cvta_generic_to_shared(smem);
    const int mat  = blockIdx.z;
    const int row0 = blockIdx.x * 128;
    const int tid  = threadIdx.x;
    const int wid  = tid >> 5, lane = tid & 31;
    const int g = lane >> 2, t = lane & 3;
    const int q2 = lane >> 3, rI = lane & 7;
    const int rb = wid * 16;

    const __nv_bfloat16* Xh = g_Ih + (size_t)mat * BND + (size_t)row0 * DDIM;
    const __nv_bfloat16* Xl = g_Il + (size_t)mat * BND + (size_t)row0 * DDIM;
    const __nv_bfloat16* Wh = g_Wh + mat * WSZ;
    const __nv_bfloat16* Wl = g_Wl + mat * WSZ;
    __nv_bfloat16* Yh = (mat == 0 ? g_Qh : (mat == 1 ? g_Kh : g_Vh));
    __nv_bfloat16* Yl = (mat == 0 ? g_Ql : (mat == 1 ? g_Kl : g_Vl));

    for (int i = tid; i < 6144; i += 256) {
        int plane = i >= 3072;
        int ii = plane ? i - 3072 : i;
        int r = ii / 24, c = ii % 24;
        const __nv_bfloat16* src = (plane ? Xl : Xh) + (size_t)r * DDIM + c * 8;
        CP_ASYNC16(SB + (plane ? PXL : PXH) + sw24(r, c), src);
    }
    for (int i = tid; i < 4608; i += 256) {
        int plane = i >= 2304;
        int ii = plane ? i - 2304 : i;
        int r = ii / 24, c = ii % 24;
        const __nv_bfloat16* src = (plane ? Wl : Wh) + (size_t)r * DDIM + c * 8;
        CP_ASYNC16(SB + (plane ? PWL : PWH) + sw24(r, c), src);
    }
    CP_COMMIT(); CP_WAIT0(); __syncthreads();

    const int rowA = rb + (lane & 15);
    const int cAadd = lane >> 4;
    const int rowW = ((q2 >> 1) << 3) + rI;
    const int cWadd = q2 & 1;

    for (int cc = 0; cc < 2; cc++) {
        float c[12][4];
        #pragma unroll
        for (int ni = 0; ni < 12; ni++)
            #pragma unroll
            for (int j = 0; j < 4; j++) c[ni][j] = 0.f;

        #pragma unroll
        for (int d0 = 0; d0 < 192; d0 += 16) {
            const int ca = (d0 >> 3) + cAadd;
            const int cw = (d0 >> 3) + cWadd;
            uint32_t ah[4], al[4], wh[6][4], wl[6][4];
            ldsm4(ah, SB + PXH + sw24(rowA, ca));
            ldsm4(al, SB + PXL + sw24(rowA, ca));
            #pragma unroll
            for (int nb = 0; nb < 6; nb++) {
                ldsm4(wh[nb], SB + PWH + sw24(nb * 16 + rowW, cw));
                ldsm4(wl[nb], SB + PWL + sw24(nb * 16 + rowW, cw));
            }
            #pragma unroll
            for (int ni = 0; ni < 12; ni++) {
                uint32_t b0h = wh[ni >> 1][(ni & 1) * 2], b1h = wh[ni >> 1][(ni & 1) * 2 + 1];
                uint32_t b0l = wl[ni >> 1][(ni & 1) * 2], b1l = wl[ni >> 1][(ni & 1) * 2 + 1];
                mma_bf16(c[ni], ah, b0h, b1h);
                mma_bf16(c[ni], ah, b0l, b1l);
                mma_bf16(c[ni], al, b0h, b1h);
            }
        }
        __syncthreads();
        if (cc == 0) {
            for (int i = tid; i < 4608; i += 256) {
                int plane = i >= 2304;
                int ii = plane ? i - 2304 : i;
                int r = ii / 24, ch = ii % 24;
                const __nv_bfloat16* src = (plane ? Wl : Wh) + (size_t)(96 + r) * DDIM + ch * 8;
                CP_ASYNC16(SB + (plane ? PWL : PWH) + sw24(r, ch), src);
            }
            CP_COMMIT();
        }
        #pragma unroll
        for (int ni = 0; ni < 12; ni++) {
            #pragma unroll
            for (int hf = 0; hf < 2; hf++) {
                int row = row0 + rb + g + hf * 8;
                int col = cc * 96 + ni * 8 + 2 * t;
                uint16_t h0, l0, h1, l1;
                hl_split(c[ni][hf * 2 + 0], h0, l0);
                hl_split(c[ni][hf * 2 + 1], h1, l1);
                size_t idx = (size_t)row * DDIM + col;
                *reinterpret_cast<uint32_t*>(&Yh[idx]) = (uint32_t)h0 | ((uint32_t)h1 << 16);
                *reinterpret_cast<uint32_t*>(&Yl[idx]) = (uint32_t)l0 | ((uint32_t)l1 << 16);
            }
        }
        if (cc == 0) { CP_WAIT0(); __syncthreads(); }
    }
}

// ---------------------------------------------------------------------------
// Kernel 2: HMMA flash attention (R9 structure), P in registers, fused norm.
// grid (32, 4), 256 threads; warp w owns q-rows 16w..16w+15.
// ---------------------------------------------------------------------------
#define QHOF 0u
#define QLOF 49152u
#define KHOF 98304u
#define KLOF 122880u
#define VHOF 147456u
#define VLOF 172032u
#define ZOF  196608u
#define ASMEM 197120

__global__ void __launch_bounds__(256, 1)
attn_kernel(const float* __restrict__ attn_mask,
            const float* __restrict__ bias,
            const float* __restrict__ o_w,
            float* __restrict__ out,
            float* __restrict__ wout) {
    extern __shared__ char smem[];
    const uint32_t SB = (uint32_t)__cvta_generic_to_shared(smem);
    float* zs = reinterpret_cast<float*>(smem + ZOF);

    const int b    = blockIdx.y;
    const int q0   = blockIdx.x * 128;
    const int tid  = threadIdx.x;
    const int wid  = tid >> 5, lane = tid & 31;
    const int g = lane >> 2, t = lane & 3;
    const int q2 = lane >> 3, rI = lane & 7;
    const int rb = wid * 16;

    const size_t bN = (size_t)b * NSEQ;
    const size_t qoff = (bN + q0) * DDIM;

    for (int i = tid; i < 6144; i += 256) {
        int plane = i >= 3072;
        int ii = plane ? i - 3072 : i;
        int r = ii / 24, c = ii % 24;
        const __nv_bfloat16* src = (plane ? g_Ql : g_Qh) + qoff + (size_t)r * DDIM + c * 8;
        CP_ASYNC16(SB + (plane ? QLOF : QHOF) + sw24(r, c), src);
    }
    for (int i = tid; i < 3072; i += 256) {
        int plane = i >= 1536;
        int ii = plane ? i - 1536 : i;
        int r = ii / 24, c = ii % 24;
        const __nv_bfloat16* src = (plane ? g_Kl : g_Kh) + (bN + r) * DDIM + c * 8;
        CP_ASYNC16(SB + (plane ? KLOF : KHOF) + sw24(r, c), src);
    }
    CP_COMMIT();

    const int rowA  = rb + (lane & 15);
    const int cAadd = lane >> 4;
    const int rowK  = ((q2 >> 1) << 3) + rI;
    const int cKadd = q2 & 1;
    const int rVadd = ((q2 & 1) << 3) + rI;
    const int cVadd = q2 >> 1;

    float o[24][4];
    #pragma unroll
    for (int ni = 0; ni < 24; ni++)
        #pragma unroll
        for (int j = 0; j < 4; j++) o[ni][j] = 0.f;
    float zacc[2] = {0.f, 0.f};

    for (int kt = 0; kt < 64; kt++) {
        const int k0 = kt * 64;
        CP_WAIT0();
        __syncthreads();

        for (int i = tid; i < 3072; i += 256) {
            int plane = i >= 1536;
            int ii = plane ? i - 1536 : i;
            int r = ii / 24, c = ii % 24;
            const __nv_bfloat16* src = (plane ? g_Vl : g_Vh) + (bN + k0 + r) * DDIM + c * 8;
            CP_ASYNC16(SB + (plane ? VLOF : VHOF) + sw24(r, c), src);
        }
        CP_COMMIT();

        // ---- S = Q @ K^T ----
        float s[8][4];
        #pragma unroll
        for (int ni = 0; ni < 8; ni++)
            #pragma unroll
            for (int j = 0; j < 4; j++) s[ni][j] = 0.f;

        #pragma unroll
        for (int d0 = 0; d0 < 192; d0 += 16) {
            const int ca = (d0 >> 3) + cAadd;
            const int ck = (d0 >> 3) + cKadd;
            uint32_t ah[4], al[4], kh[4][4], kl[4][4];
            ldsm4(ah, SB + QHOF + sw24(rowA, ca));
            ldsm4(al, SB + QLOF + sw24(rowA, ca));
            #pragma unroll
            for (int nb = 0; nb < 4; nb++) {
                ldsm4(kh[nb], SB + KHOF + sw24(nb * 16 + rowK, ck));
                ldsm4(kl[nb], SB + KLOF + sw24(nb * 16 + rowK, ck));
            }
            #pragma unroll
            for (int ni = 0; ni < 8; ni++) {
                uint32_t b0h = kh[ni >> 1][(ni & 1) * 2], b1h = kh[ni >> 1][(ni & 1) * 2 + 1];
                uint32_t b0l = kl[ni >> 1][(ni & 1) * 2], b1l = kl[ni >> 1][(ni & 1) * 2 + 1];
                mma_bf16(s[ni], ah, b0h, b1h);
                mma_bf16(s[ni], ah, b0l, b1l);
                mma_bf16(s[ni], al, b0h, b1h);
            }
        }

        // ---- epilogue ----
        uint32_t ph[4][4], pl[4][4];
        #pragma unroll
        for (int ni = 0; ni < 8; ni++) {
            const int kk = ni >> 1, sub = ni & 1;
            #pragma unroll
            for (int hf = 0; hf < 2; hf++) {
                const int rr = rb + g + hf * 8;
                const size_t off = (bN + q0 + rr) * (size_t)NSEQ + k0 + ni * 8 + 2 * t;
                float2 bb = *reinterpret_cast<const float2*>(&bias[off]);
                float2 mm = *reinterpret_cast<const float2*>(&attn_mask[off]);
                float p0 = __expf(s[ni][hf * 2 + 0] + bb.x + mm.x * NEGV);
                float p1 = __expf(s[ni][hf * 2 + 1] + bb.y + mm.y * NEGV);
                zacc[hf] += p0 + p1;
                *reinterpret_cast<float2*>(&wout[off]) = make_float2(p0, p1);
                uint16_t h0, l0, h1, l1;
                hl_split(p0, h0, l0); hl_split(p1, h1, l1);
                ph[kk][hf + sub * 2] = (uint32_t)h0 | ((uint32_t)h1 << 16);
                pl[kk][hf + sub * 2] = (uint32_t)l0 | ((uint32_t)l1 << 16);
            }
        }

        CP_WAIT0();
        __syncthreads();

        if (kt < 63) {
            const int kn = k0 + 64;
            for (int i = tid; i < 3072; i += 256) {
                int plane = i >= 1536;
                int ii = plane ? i - 1536 : i;
                int r = ii / 24, c = ii % 24;
                const __nv_bfloat16* src = (plane ? g_Kl : g_Kh) + (bN + kn + r) * DDIM + c * 8;
                CP_ASYNC16(SB + (plane ? KLOF : KHOF) + sw24(r, c), src);
            }
            CP_COMMIT();
        }

        // ---- O += P @ V ----
        #pragma unroll
        for (int nb = 0; nb < 12; nb++) {
            const int cV = cVadd + 2 * nb;
            #pragma unroll
            for (int kk = 0; kk < 4; kk++) {
                const int rV = kk * 16 + rVadd;
                uint32_t vh[4], vl[4];
                ldsm4t(vh, SB + VHOF + sw24(rV, cV));
                ldsm4t(vl, SB + VLOF + sw24(rV, cV));
                #pragma unroll
                for (int sub = 0; sub < 2; sub++) {
                    const int ni = 2 * nb + sub;
                    uint32_t b0h = vh[sub * 2], b1h = vh[sub * 2 + 1];
                    uint32_t b0l = vl[sub * 2], b1l = vl[sub * 2 + 1];
                    mma_bf16(o[ni], ph[kk], b0h, b1h);
                    mma_bf16(o[ni], ph[kk], b0l, b1l);
                    mma_bf16(o[ni], pl[kk], b0h, b1h);
                }
            }
        }
    }

    // ---- finalize Z ----
    {
        float v0 = zacc[0], v1 = zacc[1];
        v0 += __shfl_xor_sync(0xffffffffu, v0, 1);
        v0 += __shfl_xor_sync(0xffffffffu, v0, 2);
        v1 += __shfl_xor_sync(0xffffffffu, v1, 1);
        v1 += __shfl_xor_sync(0xffffffffu, v1, 2);
        if (t == 0) { zs[rb + g] = v0; zs[rb + g + 8] = v1; }
    }
    __syncthreads();

    // ---- normalized O -> smem fp32 ----
    float* OF = reinterpret_cast<float*>(smem);
    #pragma unroll
    for (int hf = 0; hf < 2; hf++) {
        const int rr = rb + g + hf * 8;
        const float iz = 1.0f / zs[rr];
        #pragma unroll
        for (int ni = 0; ni < 24; ni++) {
            const int col = ni * 8 + 2 * t;
            OF[rr * 196 + col]     = o[ni][hf * 2 + 0] * iz;
            OF[rr * 196 + col + 1] = o[ni][hf * 2 + 1] * iz;
        }
    }
    __syncthreads();

    // ---- output projection (SIMT) ----
    {
        const int ty = tid >> 4, tx = tid & 15;
        float op[8][12];
        #pragma unroll
        for (int rr = 0; rr < 8; rr++)
            #pragma unroll
            for (int c = 0; c < 12; c++) op[rr][c] = 0.f;

        #pragma unroll 2
        for (int e4 = 0; e4 < 48; e4++) {
            float oa[8][4];
            #pragma unroll
            for (int rr = 0; rr < 8; rr++) ld4(oa[rr], &OF[(ty * 8 + rr) * 196 + e4 * 4]);
            float wv[12][4];
            #pragma unroll
            for (int c = 0; c < 12; c++) ld4(wv[c], &o_w[(size_t)(tx * 12 + c) * DDIM + e4 * 4]);
            #pragma unroll
            for (int dd = 0; dd < 4; dd++)
                #pragma unroll
                for (int rr = 0; rr < 8; rr++)
                    #pragma unroll
                    for (int c = 0; c < 12; c++)
                        op[rr][c] += oa[rr][dd] * wv[c][dd];
        }

        #pragma unroll
        for (int rr = 0; rr < 8; rr++) {
            size_t off = (bN + q0 + ty * 8 + rr) * (size_t)DDIM + tx * 12;
            st4(&out[off],     &op[rr][0]);
            st4(&out[off + 4], &op[rr][4]);
            st4(&out[off + 8], &op[rr][8]);
        }
    }

    // ---- fused weight normalization: rescale this CTA's 128 rows ----
    {
        const int rl = tid >> 1, tc = tid & 1;            // 2 threads per row
        const float izr = 1.0f / zs[rl];
        float4* p = reinterpret_cast<float4*>(wout + (bN + q0 + rl) * (size_t)NSEQ);
        #pragma unroll 4
        for (int j = 0; j < 512; j++) {
            float4 v = p[tc + j * 2];
            v.x *= izr; v.y *= izr; v.z *= izr; v.w *= izr;
            p[tc + j * 2] = v;
        }
    }
}

// ---------------------------------------------------------------------------
extern "C" void kernel_launch(void* const* d_in, const int* in_sizes, int n_in,
                              void* d_out, int out_size) {
    const float* query = (const float*)d_in[0];
    const float* key_t = (const float*)d_in[1];
    const float* value = (const float*)d_in[2];
    const float* mask  = (const float*)d_in[3];
    const float* bias  = (const float*)d_in[4];
    const float* q_w   = (const float*)d_in[5];
    const float* k_w   = (const float*)d_in[6];
    const float* v_w   = (const float*)d_in[7];
    const float* o_w   = (const float*)d_in[8];

    float* out  = (float*)d_out;
    float* wout = (float*)d_out + (size_t)BATCH * NSEQ * DDIM;

    cudaFuncSetAttribute(proj_kernel, cudaFuncAttributeMaxDynamicSharedMemorySize, PSMEM);
    cudaFuncSetAttribute(attn_kernel, cudaFuncAttributeMaxDynamicSharedMemorySize, ASMEM);

    const int TOT4 = (3 * BND + 3 * WSZ) / 4;
    convert_kernel<<<(TOT4 + 255) / 256, 256>>>(query, key_t, value, q_w, k_w, v_w);

    dim3 pgrid((BATCH * NSEQ) / 128, 1, 3);
    proj_kernel<<<pgrid, 256, PSMEM>>>();

    dim3 agrid(NSEQ / 128, BATCH);
    attn_kernel<<<agrid, 256, ASMEM>>>(mask, bias, o_w, out, wout);
}

// round 12
// speedup vs baseline: 1.6779x; 1.0721x over previous
#include <cuda_runtime.h>
#include <cuda_bf16.h>
#include <cstdint>
#include <cstddef>

// ---------------------------------------------------------------------------
// SimpleAttention B=4, N=4096, D=192 — all GEMMs on mma.sync bf16 with 3-MMA
// split precision. Projections: convert -> persistent HMMA kernel (148 CTAs,
// no wave quantization). Attention: warp-owns-16-rows layout, P in registers
// (R9 structure, AT the mma.sync issue floor). Separate norm kernel (at DRAM
// roofline).
// d_out layout: [out (B*N*192) | weights (B*N*N)]
// Softmax without max-subtraction is exact-safe (|logit| <~ 33).
// ---------------------------------------------------------------------------

#define BATCH 4
#define NSEQ  4096
#define DDIM  192
#define NEGV  (-1e9f)
#define BND   (BATCH * NSEQ * DDIM)
#define WSZ   (DDIM * DDIM)

__device__ __align__(256) __nv_bfloat16 g_Ih[3 * BND];
__device__ __align__(256) __nv_bfloat16 g_Il[3 * BND];
__device__ __align__(256) __nv_bfloat16 g_Wh[3 * WSZ];
__device__ __align__(256) __nv_bfloat16 g_Wl[3 * WSZ];
__device__ __align__(256) __nv_bfloat16 g_Qh[BND];
__device__ __align__(256) __nv_bfloat16 g_Ql[BND];
__device__ __align__(256) __nv_bfloat16 g_Kh[BND];
__device__ __align__(256) __nv_bfloat16 g_Kl[BND];
__device__ __align__(256) __nv_bfloat16 g_Vh[BND];
__device__ __align__(256) __nv_bfloat16 g_Vl[BND];
__device__ float g_Z[BATCH * NSEQ];

__device__ __forceinline__ void ld4(float* d, const float* s) {
    float4 t = *reinterpret_cast<const float4*>(s);
    d[0]=t.x; d[1]=t.y; d[2]=t.z; d[3]=t.w;
}
__device__ __forceinline__ void st4(float* d, const float* s) {
    float4 t; t.x=s[0]; t.y=s[1]; t.z=s[2]; t.w=s[3];
    *reinterpret_cast<float4*>(d) = t;
}
__device__ __forceinline__ void hl_split(float x, uint16_t& h, uint16_t& l) {
    __nv_bfloat16 hh = __float2bfloat16_rn(x);
    __nv_bfloat16 ll = __float2bfloat16_rn(x - __bfloat162float(hh));
    h = __bfloat16_as_ushort(hh); l = __bfloat16_as_ushort(ll);
}

#define CP_ASYNC16(dst, src) \
    asm volatile("cp.async.cg.shared.global [%0], [%1], 16;" :: "r"(dst), "l"(src) : "memory")
#define CP_COMMIT() asm volatile("cp.async.commit_group;" ::: "memory")
#define CP_WAIT0()  asm volatile("cp.async.wait_group 0;" ::: "memory")

__device__ __forceinline__ void ldsm4(uint32_t f[4], uint32_t addr) {
    asm volatile("ldmatrix.sync.aligned.m8n8.x4.shared.b16 {%0,%1,%2,%3}, [%4];\n"
        : "=r"(f[0]), "=r"(f[1]), "=r"(f[2]), "=r"(f[3]) : "r"(addr));
}
__device__ __forceinline__ void ldsm4t(uint32_t f[4], uint32_t addr) {
    asm volatile("ldmatrix.sync.aligned.m8n8.x4.trans.shared.b16 {%0,%1,%2,%3}, [%4];\n"
        : "=r"(f[0]), "=r"(f[1]), "=r"(f[2]), "=r"(f[3]) : "r"(addr));
}
__device__ __forceinline__ void mma_bf16(float c[4], const uint32_t a[4],
                                         uint32_t b0, uint32_t b1) {
    asm volatile(
        "mma.sync.aligned.m16n8k16.row.col.f32.bf16.bf16.f32 "
        "{%0,%1,%2,%3}, {%4,%5,%6,%7}, {%8,%9}, {%0,%1,%2,%3};\n"
        : "+f"(c[0]), "+f"(c[1]), "+f"(c[2]), "+f"(c[3])
        : "r"(a[0]), "r"(a[1]), "r"(a[2]), "r"(a[3]), "r"(b0), "r"(b1));
}

__device__ __forceinline__ uint32_t sw24(int r, int c) {
    return (uint32_t)(r * 384 + ((((c) & 24) | (((c) ^ (r)) & 7)) << 4));
}

// ---------------------------------------------------------------------------
// Kernel 0: convert inputs + weights to bf16 hi/lo planes.
// ---------------------------------------------------------------------------
__global__ void convert_kernel(const float* __restrict__ q,
                               const float* __restrict__ k,
                               const float* __restrict__ v,
                               const float* __restrict__ qw,
                               const float* __restrict__ kw,
                               const float* __restrict__ vw) {
    const int TOT4 = (3 * BND + 3 * WSZ) / 4;
    int i4 = blockIdx.x * blockDim.x + threadIdx.x;
    if (i4 >= TOT4) return;
    int idx = i4 * 4;
    const float* src; __nv_bfloat16* dh; __nv_bfloat16* dl;
    if (idx < 3 * BND) {
        int r = idx / BND, o = idx - r * BND;
        src = (r == 0 ? q : (r == 1 ? k : v)) + o;
        dh = g_Ih + r * BND + o; dl = g_Il + r * BND + o;
    } else {
        int wi = idx - 3 * BND;
        int r = wi / WSZ, o = wi - r * WSZ;
        src = (r == 0 ? qw : (r == 1 ? kw : vw)) + o;
        dh = g_Wh + r * WSZ + o; dl = g_Wl + r * WSZ + o;
    }
    float4 x = *reinterpret_cast<const float4*>(src);
    uint16_t h[4], l[4];
    hl_split(x.x, h[0], l[0]); hl_split(x.y, h[1], l[1]);
    hl_split(x.z, h[2], l[2]); hl_split(x.w, h[3], l[3]);
    *reinterpret_cast<uint2*>(dh) =
        make_uint2((uint32_t)h[0] | ((uint32_t)h[1] << 16),
                   (uint32_t)h[2] | ((uint32_t)h[3] << 16));
    *reinterpret_cast<uint2*>(dl) =
        make_uint2((uint32_t)l[0] | ((uint32_t)l[1] << 16),
                   (uint32_t)l[2] | ((uint32_t)l[3] << 16));
}

// ---------------------------------------------------------------------------
// Kernel 1: persistent projections via HMMA. grid 148, each CTA loops tiles.
// Tile = 128 rows of one matrix; 384 tiles total (3 mats x 128 row-tiles).
// ---------------------------------------------------------------------------
#define PXH 0u
#define PXL 49152u
#define PWH 98304u
#define PWL 135168u
#define PSMEM 172032
#define NTILES 384

__global__ void __launch_bounds__(256, 1)
proj_kernel() {
    extern __shared__ char smem[];
    const uint32_t SB = (uint32_t)__cvta_generic_to_shared(smem);
    const int tid  = threadIdx.x;
    const int wid  = tid >> 5, lane = tid & 31;
    const int g = lane >> 2, t = lane & 3;
    const int q2 = lane >> 3, rI = lane & 7;
    const int rb = wid * 16;

    const int rowA = rb + (lane & 15);
    const int cAadd = lane >> 4;
    const int rowW = ((q2 >> 1) << 3) + rI;
    const int cWadd = q2 & 1;

    for (int tile = blockIdx.x; tile < NTILES; tile += gridDim.x) {
        const int mat  = tile >> 7;          // 128 row-tiles per matrix
        const int row0 = (tile & 127) * 128;

        const __nv_bfloat16* Xh = g_Ih + (size_t)mat * BND + (size_t)row0 * DDIM;
        const __nv_bfloat16* Xl = g_Il + (size_t)mat * BND + (size_t)row0 * DDIM;
        const __nv_bfloat16* Wh = g_Wh + mat * WSZ;
        const __nv_bfloat16* Wl = g_Wl + mat * WSZ;
        __nv_bfloat16* Yh = (mat == 0 ? g_Qh : (mat == 1 ? g_Kh : g_Vh));
        __nv_bfloat16* Yl = (mat == 0 ? g_Ql : (mat == 1 ? g_Kl : g_Vl));

        // stage X (both planes) + W chunk 0
        for (int i = tid; i < 6144; i += 256) {
            int plane = i >= 3072;
            int ii = plane ? i - 3072 : i;
            int r = ii / 24, c = ii % 24;
            const __nv_bfloat16* src = (plane ? Xl : Xh) + (size_t)r * DDIM + c * 8;
            CP_ASYNC16(SB + (plane ? PXL : PXH) + sw24(r, c), src);
        }
        for (int i = tid; i < 4608; i += 256) {
            int plane = i >= 2304;
            int ii = plane ? i - 2304 : i;
            int r = ii / 24, c = ii % 24;
            const __nv_bfloat16* src = (plane ? Wl : Wh) + (size_t)r * DDIM + c * 8;
            CP_ASYNC16(SB + (plane ? PWL : PWH) + sw24(r, c), src);
        }
        CP_COMMIT(); CP_WAIT0(); __syncthreads();

        for (int cc = 0; cc < 2; cc++) {
            float c[12][4];
            #pragma unroll
            for (int ni = 0; ni < 12; ni++)
                #pragma unroll
                for (int j = 0; j < 4; j++) c[ni][j] = 0.f;

            #pragma unroll
            for (int d0 = 0; d0 < 192; d0 += 16) {
                const int ca = (d0 >> 3) + cAadd;
                const int cw = (d0 >> 3) + cWadd;
                uint32_t ah[4], al[4], wh[6][4], wl[6][4];
                ldsm4(ah, SB + PXH + sw24(rowA, ca));
                ldsm4(al, SB + PXL + sw24(rowA, ca));
                #pragma unroll
                for (int nb = 0; nb < 6; nb++) {
                    ldsm4(wh[nb], SB + PWH + sw24(nb * 16 + rowW, cw));
                    ldsm4(wl[nb], SB + PWL + sw24(nb * 16 + rowW, cw));
                }
                #pragma unroll
                for (int ni = 0; ni < 12; ni++) {
                    uint32_t b0h = wh[ni >> 1][(ni & 1) * 2], b1h = wh[ni >> 1][(ni & 1) * 2 + 1];
                    uint32_t b0l = wl[ni >> 1][(ni & 1) * 2], b1l = wl[ni >> 1][(ni & 1) * 2 + 1];
                    mma_bf16(c[ni], ah, b0h, b1h);
                    mma_bf16(c[ni], ah, b0l, b1l);
                    mma_bf16(c[ni], al, b0h, b1h);
                }
            }
            __syncthreads();
            if (cc == 0) {
                for (int i = tid; i < 4608; i += 256) {
                    int plane = i >= 2304;
                    int ii = plane ? i - 2304 : i;
                    int r = ii / 24, ch = ii % 24;
                    const __nv_bfloat16* src = (plane ? Wl : Wh) + (size_t)(96 + r) * DDIM + ch * 8;
                    CP_ASYNC16(SB + (plane ? PWL : PWH) + sw24(r, ch), src);
                }
                CP_COMMIT();
            }
            #pragma unroll
            for (int ni = 0; ni < 12; ni++) {
                #pragma unroll
                for (int hf = 0; hf < 2; hf++) {
                    int row = row0 + rb + g + hf * 8;
                    int col = cc * 96 + ni * 8 + 2 * t;
                    uint16_t h0, l0, h1, l1;
                    hl_split(c[ni][hf * 2 + 0], h0, l0);
                    hl_split(c[ni][hf * 2 + 1], h1, l1);
                    size_t idx = (size_t)row * DDIM + col;
                    *reinterpret_cast<uint32_t*>(&Yh[idx]) = (uint32_t)h0 | ((uint32_t)h1 << 16);
                    *reinterpret_cast<uint32_t*>(&Yl[idx]) = (uint32_t)l0 | ((uint32_t)l1 << 16);
                }
            }
            if (cc == 0) { CP_WAIT0(); __syncthreads(); }
        }
        __syncthreads();   // protect smem before next tile's staging
    }
}

// ---------------------------------------------------------------------------
// Kernel 2: HMMA flash attention (R9 structure), P in registers.
// grid (32, 4), 256 threads; warp w owns q-rows 16w..16w+15.
// ---------------------------------------------------------------------------
#define QHOF 0u
#define QLOF 49152u
#define KHOF 98304u
#define KLOF 122880u
#define VHOF 147456u
#define VLOF 172032u
#define ZOF  196608u
#define ASMEM 197120

__global__ void __launch_bounds__(256, 1)
attn_kernel(const float* __restrict__ attn_mask,
            const float* __restrict__ bias,
            const float* __restrict__ o_w,
            float* __restrict__ out,
            float* __restrict__ wout) {
    extern __shared__ char smem[];
    const uint32_t SB = (uint32_t)__cvta_generic_to_shared(smem);
    float* zs = reinterpret_cast<float*>(smem + ZOF);

    const int b    = blockIdx.y;
    const int q0   = blockIdx.x * 128;
    const int tid  = threadIdx.x;
    const int wid  = tid >> 5, lane = tid & 31;
    const int g = lane >> 2, t = lane & 3;
    const int q2 = lane >> 3, rI = lane & 7;
    const int rb = wid * 16;

    const size_t bN = (size_t)b * NSEQ;
    const size_t qoff = (bN + q0) * DDIM;

    for (int i = tid; i < 6144; i += 256) {
        int plane = i >= 3072;
        int ii = plane ? i - 3072 : i;
        int r = ii / 24, c = ii % 24;
        const __nv_bfloat16* src = (plane ? g_Ql : g_Qh) + qoff + (size_t)r * DDIM + c * 8;
        CP_ASYNC16(SB + (plane ? QLOF : QHOF) + sw24(r, c), src);
    }
    for (int i = tid; i < 3072; i += 256) {
        int plane = i >= 1536;
        int ii = plane ? i - 1536 : i;
        int r = ii / 24, c = ii % 24;
        const __nv_bfloat16* src = (plane ? g_Kl : g_Kh) + (bN + r) * DDIM + c * 8;
        CP_ASYNC16(SB + (plane ? KLOF : KHOF) + sw24(r, c), src);
    }
    CP_COMMIT();

    const int rowA  = rb + (lane & 15);
    const int cAadd = lane >> 4;
    const int rowK  = ((q2 >> 1) << 3) + rI;
    const int cKadd = q2 & 1;
    const int rVadd = ((q2 & 1) << 3) + rI;
    const int cVadd = q2 >> 1;

    float o[24][4];
    #pragma unroll
    for (int ni = 0; ni < 24; ni++)
        #pragma unroll
        for (int j = 0; j < 4; j++) o[ni][j] = 0.f;
    float zacc[2] = {0.f, 0.f};

    for (int kt = 0; kt < 64; kt++) {
        const int k0 = kt * 64;
        CP_WAIT0();
        __syncthreads();

        for (int i = tid; i < 3072; i += 256) {
            int plane = i >= 1536;
            int ii = plane ? i - 1536 : i;
            int r = ii / 24, c = ii % 24;
            const __nv_bfloat16* src = (plane ? g_Vl : g_Vh) + (bN + k0 + r) * DDIM + c * 8;
            CP_ASYNC16(SB + (plane ? VLOF : VHOF) + sw24(r, c), src);
        }
        CP_COMMIT();

        // ---- S = Q @ K^T ----
        float s[8][4];
        #pragma unroll
        for (int ni = 0; ni < 8; ni++)
            #pragma unroll
            for (int j = 0; j < 4; j++) s[ni][j] = 0.f;

        #pragma unroll
        for (int d0 = 0; d0 < 192; d0 += 16) {
            const int ca = (d0 >> 3) + cAadd;
            const int ck = (d0 >> 3) + cKadd;
            uint32_t ah[4], al[4], kh[4][4], kl[4][4];
            ldsm4(ah, SB + QHOF + sw24(rowA, ca));
            ldsm4(al, SB + QLOF + sw24(rowA, ca));
            #pragma unroll
            for (int nb = 0; nb < 4; nb++) {
                ldsm4(kh[nb], SB + KHOF + sw24(nb * 16 + rowK, ck));
                ldsm4(kl[nb], SB + KLOF + sw24(nb * 16 + rowK, ck));
            }
            #pragma unroll
            for (int ni = 0; ni < 8; ni++) {
                uint32_t b0h = kh[ni >> 1][(ni & 1) * 2], b1h = kh[ni >> 1][(ni & 1) * 2 + 1];
                uint32_t b0l = kl[ni >> 1][(ni & 1) * 2], b1l = kl[ni >> 1][(ni & 1) * 2 + 1];
                mma_bf16(s[ni], ah, b0h, b1h);
                mma_bf16(s[ni], ah, b0l, b1l);
                mma_bf16(s[ni], al, b0h, b1h);
            }
        }

        // ---- epilogue: exp -> wout + P fragments in registers ----
        uint32_t ph[4][4], pl[4][4];
        #pragma unroll
        for (int ni = 0; ni < 8; ni++) {
            const int kk = ni >> 1, sub = ni & 1;
            #pragma unroll
            for (int hf = 0; hf < 2; hf++) {
                const int rr = rb + g + hf * 8;
                const size_t off = (bN + q0 + rr) * (size_t)NSEQ + k0 + ni * 8 + 2 * t;
                float2 bb = *reinterpret_cast<const float2*>(&bias[off]);
                float2 mm = *reinterpret_cast<const float2*>(&attn_mask[off]);
                float p0 = __expf(s[ni][hf * 2 + 0] + bb.x + mm.x * NEGV);
                float p1 = __expf(s[ni][hf * 2 + 1] + bb.y + mm.y * NEGV);
                zacc[hf] += p0 + p1;
                *reinterpret_cast<float2*>(&wout[off]) = make_float2(p0, p1);
                uint16_t h0, l0, h1, l1;
                hl_split(p0, h0, l0); hl_split(p1, h1, l1);
                ph[kk][hf + sub * 2] = (uint32_t)h0 | ((uint32_t)h1 << 16);
                pl[kk][hf + sub * 2] = (uint32_t)l0 | ((uint32_t)l1 << 16);
            }
        }

        CP_WAIT0();
        __syncthreads();

        if (kt < 63) {
            const int kn = k0 + 64;
            for (int i = tid; i < 3072; i += 256) {
                int plane = i >= 1536;
                int ii = plane ? i - 1536 : i;
                int r = ii / 24, c = ii % 24;
                const __nv_bfloat16* src = (plane ? g_Kl : g_Kh) + (bN + kn + r) * DDIM + c * 8;
                CP_ASYNC16(SB + (plane ? KLOF : KHOF) + sw24(r, c), src);
            }
            CP_COMMIT();
        }

        // ---- O += P @ V ----
        #pragma unroll
        for (int nb = 0; nb < 12; nb++) {
            const int cV = cVadd + 2 * nb;
            #pragma unroll
            for (int kk = 0; kk < 4; kk++) {
                const int rV = kk * 16 + rVadd;
                uint32_t vh[4], vl[4];
                ldsm4t(vh, SB + VHOF + sw24(rV, cV));
                ldsm4t(vl, SB + VLOF + sw24(rV, cV));
                #pragma unroll
                for (int sub = 0; sub < 2; sub++) {
                    const int ni = 2 * nb + sub;
                    uint32_t b0h = vh[sub * 2], b1h = vh[sub * 2 + 1];
                    uint32_t b0l = vl[sub * 2], b1l = vl[sub * 2 + 1];
                    mma_bf16(o[ni], ph[kk], b0h, b1h);
                    mma_bf16(o[ni], ph[kk], b0l, b1l);
                    mma_bf16(o[ni], pl[kk], b0h, b1h);
                }
            }
        }
    }

    // ---- finalize Z ----
    {
        float v0 = zacc[0], v1 = zacc[1];
        v0 += __shfl_xor_sync(0xffffffffu, v0, 1);
        v0 += __shfl_xor_sync(0xffffffffu, v0, 2);
        v1 += __shfl_xor_sync(0xffffffffu, v1, 1);
        v1 += __shfl_xor_sync(0xffffffffu, v1, 2);
        if (t == 0) { zs[rb + g] = v0; zs[rb + g + 8] = v1; }
    }
    __syncthreads();
    if (tid < 128) g_Z[bN + q0 + tid] = zs[tid];

    // ---- normalized O -> smem fp32 ----
    float* OF = reinterpret_cast<float*>(smem);
    #pragma unroll
    for (int hf = 0; hf < 2; hf++) {
        const int rr = rb + g + hf * 8;
        const float iz = 1.0f / zs[rr];
        #pragma unroll
        for (int ni = 0; ni < 24; ni++) {
            const int col = ni * 8 + 2 * t;
            OF[rr * 196 + col]     = o[ni][hf * 2 + 0] * iz;
            OF[rr * 196 + col + 1] = o[ni][hf * 2 + 1] * iz;
        }
    }
    __syncthreads();

    // ---- output projection (SIMT) ----
    {
        const int ty = tid >> 4, tx = tid & 15;
        float op[8][12];
        #pragma unroll
        for (int rr = 0; rr < 8; rr++)
            #pragma unroll
            for (int c = 0; c < 12; c++) op[rr][c] = 0.f;

        #pragma unroll 2
        for (int e4 = 0; e4 < 48; e4++) {
            float oa[8][4];
            #pragma unroll
            for (int rr = 0; rr < 8; rr++) ld4(oa[rr], &OF[(ty * 8 + rr) * 196 + e4 * 4]);
            float wv[12][4];
            #pragma unroll
            for (int c = 0; c < 12; c++) ld4(wv[c], &o_w[(size_t)(tx * 12 + c) * DDIM + e4 * 4]);
            #pragma unroll
            for (int dd = 0; dd < 4; dd++)
                #pragma unroll
                for (int rr = 0; rr < 8; rr++)
                    #pragma unroll
                    for (int c = 0; c < 12; c++)
                        op[rr][c] += oa[rr][dd] * wv[c][dd];
        }

        #pragma unroll
        for (int rr = 0; rr < 8; rr++) {
            size_t off = (bN + q0 + ty * 8 + rr) * (size_t)DDIM + tx * 12;
            st4(&out[off],     &op[rr][0]);
            st4(&out[off + 4], &op[rr][4]);
            st4(&out[off + 8], &op[rr][8]);
        }
    }
}

// ---------------------------------------------------------------------------
// Kernel 3: normalize weights in place (at DRAM roofline; keep separate).
// ---------------------------------------------------------------------------
__global__ void norm_kernel(float* __restrict__ wout) {
    const int row = blockIdx.x;
    const float inv = 1.0f / g_Z[row];
    float4* p = reinterpret_cast<float4*>(wout) + (size_t)row * (NSEQ / 4);
    const int t = threadIdx.x;
    #pragma unroll
    for (int j = 0; j < 4; j++) {
        float4 v = p[t + j * 256];
        v.x *= inv; v.y *= inv; v.z *= inv; v.w *= inv;
        p[t + j * 256] = v;
    }
}

// ---------------------------------------------------------------------------
extern "C" void kernel_launch(void* const* d_in, const int* in_sizes, int n_in,
                              void* d_out, int out_size) {
    const float* query = (const float*)d_in[0];
    const float* key_t = (const float*)d_in[1];
    const float* value = (const float*)d_in[2];
    const float* mask  = (const float*)d_in[3];
    const float* bias  = (const float*)d_in[4];
    const float* q_w   = (const float*)d_in[5];
    const float* k_w   = (const float*)d_in[6];
    const float* v_w   = (const float*)d_in[7];
    const float* o_w   = (const float*)d_in[8];

    float* out  = (float*)d_out;
    float* wout = (float*)d_out + (size_t)BATCH * NSEQ * DDIM;

    cudaFuncSetAttribute(proj_kernel, cudaFuncAttributeMaxDynamicSharedMemorySize, PSMEM);
    cudaFuncSetAttribute(attn_kernel, cudaFuncAttributeMaxDynamicSharedMemorySize, ASMEM);

    const int TOT4 = (3 * BND + 3 * WSZ) / 4;
    convert_kernel<<<(TOT4 + 255) / 256, 256>>>(query, key_t, value, q_w, k_w, v_w);

    proj_kernel<<<148, 256, PSMEM>>>();

    dim3 agrid(NSEQ / 128, BATCH);
    attn_kernel<<<agrid, 256, ASMEM>>>(mask, bias, o_w, out, wout);

    norm_kernel<<<BATCH * NSEQ, 256>>>(wout);
}